// round 14
// baseline (speedup 1.0000x reference)
#include <cuda_runtime.h>

#define HD    64
#define LSEQ  2048
#define BATCH 16
#define NTOK  (BATCH * LSEQ)
#define RING  32

typedef unsigned long long ull;

// Scratch (device globals, zero-initialized; pad regions never written -> stay 0)
__device__ float g_h[(NTOK + 16) * HD];   // post-LN hidden states (+pad)
__device__ float g_gram[(NTOK + 16) * 8]; // per token: g_1..g_7 (g_j = k_{t-j}.k_t), invd
__device__ float g_ctx[BATCH * HD];       // ctx = M_final . q
__device__ unsigned int g_cnt[BATCH];     // scan completion counters (self-resetting)

// ---------------- packed f32x2 helpers (sm_103a) ----------------
__device__ __forceinline__ ull ffma2(ull a, ull b, ull c) {
    ull d;
    asm("fma.rn.f32x2 %0, %1, %2, %3;" : "=l"(d) : "l"(a), "l"(b), "l"(c));
    return d;
}
__device__ __forceinline__ ull fadd2(ull a, ull b) {
    ull d;
    asm("add.rn.f32x2 %0, %1, %2;" : "=l"(d) : "l"(a), "l"(b));
    return d;
}
__device__ __forceinline__ ull fmul2(ull a, ull b) {
    ull d;
    asm("mul.rn.f32x2 %0, %1, %2;" : "=l"(d) : "l"(a), "l"(b));
    return d;
}
__device__ __forceinline__ ull fpack2(float lo, float hi) {
    ull d;
    asm("mov.b64 %0, {%1, %2};" : "=l"(d) : "f"(lo), "f"(hi));
    return d;
}
__device__ __forceinline__ void funpack2(ull v, float& lo, float& hi) {
    asm("mov.b64 {%0, %1}, %2;" : "=f"(lo), "=f"(hi) : "l"(v));
}
__device__ __forceinline__ ull fdup2(float x) { return fpack2(x, x); }

// ---------------------------------------------------------------
// Phase 1 (v3): register-blocked packed MLP+LN with PRE-DUPLICATED
// weights in shared (f32x2 ull arrays) — no per-use dup MOVs.
// 8 warps/block; each warp processes an 8-token tile.
// ---------------------------------------------------------------
#define HP_STRIDE 10   // pad: row stride (floats) for h tile
#define AP_STRIDE 10   // pad: row stride (floats) for activation tile

__global__ __launch_bounds__(256) void phase1_kernel(
    const int*   __restrict__ seq,
    const float* __restrict__ embed,
    const float* __restrict__ W1,
    const float* __restrict__ b1,
    const float* __restrict__ W2,
    const float* __restrict__ b2,
    const float* __restrict__ gamma,
    const float* __restrict__ beta)
{
    extern __shared__ __align__(16) ull dsmu[];
    ull* W1d = dsmu;              // [64*128] duplicated
    ull* W2d = dsmu + 64 * 128;   // [128*64] duplicated

    __shared__ __align__(16) ull b1d[128];
    __shared__ __align__(16) ull b2d[64], gsd[64], bsd[64];
    __shared__ __align__(8) float hpf[8][64][HP_STRIDE];   // h tile  [dim][token]
    __shared__ __align__(8) float apf[8][128][AP_STRIDE];  // act tile [m][token]

    const int tid = threadIdx.x;
    for (int i = tid; i < 64 * 128; i += 256) W1d[i] = fdup2(W1[i]);
    for (int i = tid; i < 128 * 64; i += 256) W2d[i] = fdup2(W2[i]);
    if (tid < 128) b1d[tid] = fdup2(b1[tid]);
    if (tid < 64) {
        b2d[tid] = fdup2(b2[tid]);
        gsd[tid] = fdup2(gamma[tid]);
        bsd[tid] = fdup2(beta[tid]);
    }
    __syncthreads();

    const int w    = tid >> 5;
    const int lane = tid & 31;
    const int gw   = blockIdx.x * 8 + w;     // global warp id
    const int nw   = gridDim.x * 8;

    const ull negone = fdup2(-1.0f);
    const ull inv64  = fdup2(1.0f / 64.0f);

    for (int tile = gw; tile < NTOK / 8; tile += nw) {
        const int tok0 = tile * 8;

        // ---- gather: hpf[j][tt] = embed[seq[tok0+tt]][j] ----
        #pragma unroll
        for (int tt = 0; tt < 8; tt++) {
            const int v = seq[tok0 + tt];
            hpf[w][lane][tt]      = embed[v * 64 + lane];
            hpf[w][lane + 32][tt] = embed[v * 64 + 32 + lane];
        }
        __syncwarp();

        // ---- layer 1: a[m] = relu(sum_j h[j]*W1[j,m] + b1[m]) ----
        ull acc[4][4];
        {
            const ulonglong2* bp = (const ulonglong2*)&b1d[lane * 4];
            const ulonglong2 bA = bp[0], bB = bp[1];
            #pragma unroll
            for (int p = 0; p < 4; p++) {
                acc[p][0] = bA.x; acc[p][1] = bA.y;
                acc[p][2] = bB.x; acc[p][3] = bB.y;
            }
        }
        #pragma unroll 8
        for (int j = 0; j < 64; j++) {
            const ulonglong2* wp = (const ulonglong2*)&W1d[j * 128 + lane * 4];
            const ulonglong2 wA = wp[0], wB = wp[1];
            #pragma unroll
            for (int p = 0; p < 4; p++) {
                const ull hj = *(const ull*)&hpf[w][j][2 * p];  // broadcast
                acc[p][0] = ffma2(hj, wA.x, acc[p][0]);
                acc[p][1] = ffma2(hj, wA.y, acc[p][1]);
                acc[p][2] = ffma2(hj, wB.x, acc[p][2]);
                acc[p][3] = ffma2(hj, wB.y, acc[p][3]);
            }
        }
        // relu + store activations
        #pragma unroll
        for (int p = 0; p < 4; p++)
            #pragma unroll
            for (int o = 0; o < 4; o++) {
                float lo, hi;
                funpack2(acc[p][o], lo, hi);
                *(ull*)&apf[w][lane * 4 + o][2 * p] =
                    fpack2(fmaxf(lo, 0.f), fmaxf(hi, 0.f));
            }
        __syncwarp();

        // ---- layer 2: f[i] = sum_m a[m]*W2[m,i] + b2[i]; lane owns i=2l,2l+1 ----
        ull a2[2][4];
        {
            const ulonglong2 bb2 = *(const ulonglong2*)&b2d[2 * lane];
            #pragma unroll
            for (int p = 0; p < 4; p++) {
                a2[0][p] = bb2.x;
                a2[1][p] = bb2.y;
            }
        }
        #pragma unroll 8
        for (int m = 0; m < 128; m++) {
            const ulonglong2 wd = *(const ulonglong2*)&W2d[m * 64 + 2 * lane];
            #pragma unroll
            for (int p = 0; p < 4; p++) {
                const ull am = *(const ull*)&apf[w][m][2 * p];  // broadcast
                a2[0][p] = ffma2(am, wd.x, a2[0][p]);
                a2[1][p] = ffma2(am, wd.y, a2[1][p]);
            }
        }

        // ---- residual + LayerNorm (packed over token pairs) ----
        ull xp[2][4];
        #pragma unroll
        for (int o = 0; o < 2; o++)
            #pragma unroll
            for (int p = 0; p < 4; p++) {
                const ull hv = *(const ull*)&hpf[w][2 * lane + o][2 * p];
                xp[o][p] = fadd2(a2[o][p], hv);
            }

        ull mu2[4], rstd2[4];
        #pragma unroll
        for (int p = 0; p < 4; p++) {
            ull s = fadd2(xp[0][p], xp[1][p]);
            #pragma unroll
            for (int off = 16; off > 0; off >>= 1) {
                float lo, hi;
                funpack2(s, lo, hi);
                lo += __shfl_xor_sync(0xffffffffu, lo, off);
                hi += __shfl_xor_sync(0xffffffffu, hi, off);
                s = fpack2(lo, hi);
            }
            mu2[p] = fmul2(s, inv64);
        }
        #pragma unroll
        for (int p = 0; p < 4; p++) {
            const ull d0 = ffma2(mu2[p], negone, xp[0][p]);
            const ull d1 = ffma2(mu2[p], negone, xp[1][p]);
            ull s = fadd2(ffma2(d0, d0, 0ull), ffma2(d1, d1, 0ull));
            #pragma unroll
            for (int off = 16; off > 0; off >>= 1) {
                float lo, hi;
                funpack2(s, lo, hi);
                lo += __shfl_xor_sync(0xffffffffu, lo, off);
                hi += __shfl_xor_sync(0xffffffffu, hi, off);
                s = fpack2(lo, hi);
            }
            float vlo, vhi;
            funpack2(fmul2(s, inv64), vlo, vhi);
            rstd2[p] = fpack2(rsqrtf(vlo + 1e-5f), rsqrtf(vhi + 1e-5f));
        }
        #pragma unroll
        for (int o = 0; o < 2; o++) {
            const ull gm = gsd[2 * lane + o];
            const ull bt = bsd[2 * lane + o];
            #pragma unroll
            for (int p = 0; p < 4; p++) {
                const ull d  = ffma2(mu2[p], negone, xp[o][p]);
                const ull t  = fmul2(fmul2(d, rstd2[p]), gm);
                const ull y  = fadd2(t, bt);
                float lo, hi;
                funpack2(y, lo, hi);
                g_h[(tok0 + 2 * p)     * 64 + 2 * lane + o] = lo;
                g_h[(tok0 + 2 * p + 1) * 64 + 2 * lane + o] = hi;
            }
        }
        __syncwarp();
    }
}

// ---------------------------------------------------------------
// Phase 1.5: Gram lookahead. Warp per token; 8 four-lane groups,
// group j computes dot(k_t, k_{t-j}); j=0 -> invd in slot 7.
// ---------------------------------------------------------------
__global__ __launch_bounds__(256) void gram_kernel()
{
    const int wid  = (blockIdx.x * 256 + threadIdx.x) >> 5;
    const int lane = threadIdx.x & 31;
    if (wid >= NTOK) return;
    const int t   = wid;
    const int pos = t & (LSEQ - 1);
    const int j   = lane >> 2;     // 0..7
    const int sub = lane & 3;      // elems [sub*16, sub*16+16)

    const bool valid = (j == 0) || (pos >= j);
    const int  tm    = valid ? (t - j) : t;

    const ull* pa = (const ull*)&g_h[(size_t)t  * 64 + sub * 16];
    const ull* pb = (const ull*)&g_h[(size_t)tm * 64 + sub * 16];

    ull a0 = 0ull, a1 = 0ull, a2 = 0ull, a3 = 0ull;
    #pragma unroll
    for (int i = 0; i < 8; i += 4) {
        a0 = ffma2(pa[i],     pb[i],     a0);
        a1 = ffma2(pa[i + 1], pb[i + 1], a1);
        a2 = ffma2(pa[i + 2], pb[i + 2], a2);
        a3 = ffma2(pa[i + 3], pb[i + 3], a3);
    }
    float lo, hi;
    funpack2(fadd2(fadd2(a0, a1), fadd2(a2, a3)), lo, hi);
    float s = lo + hi;
    s += __shfl_xor_sync(0xffffffffu, s, 1);
    s += __shfl_xor_sync(0xffffffffu, s, 2);

    if (sub == 0) {
        if (j == 0) g_gram[(size_t)t * 8 + 7] = 1.0f / (s + 1e-6f);
        else        g_gram[(size_t)t * 8 + (j - 1)] = valid ? s : 0.0f;
    }
}

// ---------------------------------------------------------------
// Phase 2: delta-rule scan, rank-8 windows, pipelined dots,
// with FUSED output projection (last block per batch does it).
// ---------------------------------------------------------------
__global__ __launch_bounds__(32, 1) void scan_kernel(
    const float* __restrict__ Wr, const float* __restrict__ br,
    const float* __restrict__ Wo, const float* __restrict__ bo,
    float* __restrict__ out)
{
    __shared__ __align__(16) float smk[RING][64];
    __shared__ __align__(16) float smaux[RING][8];  // g1..g7, invd
    __shared__ float prs[64];

    const int bb   = blockIdx.x >> 4;
    const int rg   = blockIdx.x & 15;
    const int tid  = threadIdx.x;   // 0..31
    const int r    = tid >> 3;      // row within group 0..3
    const int c8   = tid & 7;       // column eighth
    const int e    = rg * 4 + r;

    const float* __restrict__ hb  = g_h    + (size_t)bb * LSEQ * HD;
    const float* __restrict__ gga = g_gram + (size_t)bb * LSEQ * 8;

    #pragma unroll
    for (int i = tid; i < 24 * 16; i += 32) {
        const int tok = i >> 4, seg = i & 15;
        *(float4*)&smk[tok][seg * 4] = *(const float4*)&hb[tok * 64 + seg * 4];
    }
    #pragma unroll
    for (int i = tid; i < 48; i += 32) {
        const int tok = i >> 1, hf = i & 1;
        *(float4*)&smaux[tok][hf * 4] = *(const float4*)&gga[tok * 8 + hf * 4];
    }
    __syncwarp();

    ull M[4];
    #pragma unroll
    for (int i = 0; i < 4; i++) M[i] = 0ull;

    ull kreg[8][4];
    #pragma unroll
    for (int u = 0; u < 8; u++) {
        const ulonglong2* kp = (const ulonglong2*)&smk[u][c8 * 8];
        const ulonglong2 k0 = kp[0], k1 = kp[1];
        kreg[u][0] = k0.x; kreg[u][1] = k0.y;
        kreg[u][2] = k1.x; kreg[u][3] = k1.y;
    }

    float c[8], dv[8];
    #pragma unroll
    for (int i = 0; i < 8; i++) c[i] = 0.0f;

    #pragma unroll 1
    for (int tb = 0; tb <= 2032; tb += 8) {
        #pragma unroll
        for (int u = 0; u < 8; u++) {
            const int sl = (tb + u) & (RING - 1);
            const float  ke = smk[sl][e];
            const float4 gA = *(const float4*)&smaux[sl][0];
            const float4 gB = *(const float4*)&smaux[sl][4];
            float S = c[u];
            if (u >= 7) S = fmaf(dv[u - 7], gB.z, S);
            if (u >= 6) S = fmaf(dv[u - 6], gB.y, S);
            if (u >= 5) S = fmaf(dv[u - 5], gB.x, S);
            if (u >= 4) S = fmaf(dv[u - 4], gA.w, S);
            if (u >= 3) S = fmaf(dv[u - 3], gA.z, S);
            if (u >= 2) S = fmaf(dv[u - 2], gA.y, S);
            if (u >= 1) S = fmaf(dv[u - 1], gA.x, S);
            dv[u] = fmaf(-gB.w, S, ke);
        }

        #pragma unroll
        for (int u = 0; u < 8; u++) {
            const ull dvp = fpack2(dv[u], dv[u]);
            M[0] = ffma2(dvp, kreg[u][0], M[0]);
            M[1] = ffma2(dvp, kreg[u][1], M[1]);
            M[2] = ffma2(dvp, kreg[u][2], M[2]);
            M[3] = ffma2(dvp, kreg[u][3], M[3]);
        }

        #pragma unroll
        for (int u = 0; u < 8; u++) {
            const ulonglong2* kd =
                (const ulonglong2*)&smk[(tb + 8 + u) & (RING - 1)][c8 * 8];
            const ulonglong2 k0 = kd[0], k1 = kd[1];
            kreg[u][0] = k0.x; kreg[u][1] = k0.y;
            kreg[u][2] = k1.x; kreg[u][3] = k1.y;
            ull a0 = ffma2(M[0], k0.x, 0ull);
            ull a1 = ffma2(M[1], k0.y, 0ull);
            a0 = ffma2(M[2], k1.x, a0);
            a1 = ffma2(M[3], k1.y, a1);
            float lo, hi;
            funpack2(fadd2(a0, a1), lo, hi);
            c[u] = lo + hi;
        }
        #pragma unroll
        for (int u = 0; u < 8; u++) c[u] += __shfl_xor_sync(0xffffffffu, c[u], 1);
        #pragma unroll
        for (int u = 0; u < 8; u++) c[u] += __shfl_xor_sync(0xffffffffu, c[u], 2);
        #pragma unroll
        for (int u = 0; u < 8; u++) c[u] += __shfl_xor_sync(0xffffffffu, c[u], 4);

        #pragma unroll
        for (int w = 0; w < 4; w++) {
            const int i = w * 32 + tid;
            const int tok = tb + 24 + (i >> 4);
            const int seg = i & 15;
            *(float4*)&smk[tok & (RING - 1)][seg * 4] =
                *(const float4*)&hb[tok * 64 + seg * 4];
        }
        if (tid < 16) {
            const int tok = tb + 24 + (tid >> 1);
            const int hf  = tid & 1;
            *(float4*)&smaux[tok & (RING - 1)][hf * 4] =
                *(const float4*)&gga[tok * 8 + hf * 4];
        }
        __syncwarp();
    }

    {
        const int tb = 2040;
        #pragma unroll
        for (int u = 0; u < 7; u++) {
            const int sl = (tb + u) & (RING - 1);
            const float  ke = smk[sl][e];
            const float4 gA = *(const float4*)&smaux[sl][0];
            const float4 gB = *(const float4*)&smaux[sl][4];
            float S = c[u];
            if (u >= 6) S = fmaf(dv[u - 6], gB.y, S);
            if (u >= 5) S = fmaf(dv[u - 5], gB.x, S);
            if (u >= 4) S = fmaf(dv[u - 4], gA.w, S);
            if (u >= 3) S = fmaf(dv[u - 3], gA.z, S);
            if (u >= 2) S = fmaf(dv[u - 2], gA.y, S);
            if (u >= 1) S = fmaf(dv[u - 1], gA.x, S);
            dv[u] = fmaf(-gB.w, S, ke);
        }

        const float4 gA = *(const float4*)&smaux[2047 & (RING - 1)][0];
        const float4 gB = *(const float4*)&smaux[2047 & (RING - 1)][4];
        float S = c[7];
        S = fmaf(dv[0], gB.z, S);
        S = fmaf(dv[1], gB.y, S);
        S = fmaf(dv[2], gB.x, S);
        S = fmaf(dv[3], gA.w, S);
        S = fmaf(dv[4], gA.z, S);
        S = fmaf(dv[5], gA.y, S);
        S = fmaf(dv[6], gA.x, S);
        if (c8 == 0) g_ctx[bb * 64 + e] = S;
    }

    // ---- fused projection: last block of this batch computes out[bb] ----
    __syncwarp();
    unsigned done = 0;
    if (tid == 0) {
        __threadfence();
        done = (atomicAdd(&g_cnt[bb], 1u) == 15u) ? 1u : 0u;
    }
    done = __shfl_sync(0xffffffffu, done, 0);
    if (done) {
        __threadfence();                    // acquire all g_ctx writes
        if (tid == 0) g_cnt[bb] = 0;        // reset for next graph replay
        const float* ctx = g_ctx + bb * 64;
        float r0 = br[tid], r1 = br[tid + 32];
        #pragma unroll 8
        for (int j = 0; j < 64; j++) {
            const float cj = ctx[j];
            r0 = fmaf(cj, Wr[j * 64 + tid], r0);
            r1 = fmaf(cj, Wr[j * 64 + tid + 32], r1);
        }
        prs[tid] = r0;
        prs[tid + 32] = r1;
        __syncwarp();
        float o0 = bo[tid], o1 = bo[tid + 32];
        #pragma unroll 8
        for (int j = 0; j < 64; j++) {
            const float rj = prs[j];
            o0 = fmaf(rj, Wo[j * 64 + tid], o0);
            o1 = fmaf(rj, Wo[j * 64 + tid + 32], o1);
        }
        out[bb * 64 + tid]      = o0;
        out[bb * 64 + tid + 32] = o1;
    }
}

// ---------------------------------------------------------------
extern "C" void kernel_launch(void* const* d_in, const int* in_sizes, int n_in,
                              void* d_out, int out_size)
{
    const int*   seq   = (const int*)  d_in[0];
    const float* embed = (const float*)d_in[1];
    const float* W1    = (const float*)d_in[2];
    const float* b1    = (const float*)d_in[3];
    const float* W2    = (const float*)d_in[4];
    const float* b2    = (const float*)d_in[5];
    const float* gamma = (const float*)d_in[6];
    const float* beta  = (const float*)d_in[7];
    const float* Wr    = (const float*)d_in[8];
    const float* br    = (const float*)d_in[9];
    const float* Wo    = (const float*)d_in[10];
    const float* bo    = (const float*)d_in[11];
    float* out = (float*)d_out;

    (void)in_sizes; (void)n_in; (void)out_size;

    cudaFuncSetAttribute(phase1_kernel,
                         cudaFuncAttributeMaxDynamicSharedMemorySize, 131072);
    phase1_kernel<<<148, 256, 131072>>>(seq, embed, W1, b1, W2, b2, gamma, beta);
    gram_kernel<<<NTOK / 8, 256>>>();
    scan_kernel<<<BATCH * 16, 32>>>(Wr, br, Wo, bo, out);
}

// round 15
// speedup vs baseline: 1.6904x; 1.6904x over previous
#include <cuda_runtime.h>

#define HD    64
#define LSEQ  2048
#define BATCH 16
#define NTOK  (BATCH * LSEQ)
#define RING  32

typedef unsigned long long ull;

// Scratch (device globals, zero-initialized; pad regions never written -> stay 0)
__device__ float g_h[(NTOK + 16) * HD];   // post-LN hidden states (+pad)
__device__ float g_gram[(NTOK + 16) * 8]; // per token: g_1..g_7 (g_j = k_{t-j}.k_t), invd
__device__ float g_ctx[BATCH * HD];       // ctx = M_final . q

// ---------------- packed f32x2 helpers (sm_103a) ----------------
__device__ __forceinline__ ull ffma2(ull a, ull b, ull c) {
    ull d;
    asm("fma.rn.f32x2 %0, %1, %2, %3;" : "=l"(d) : "l"(a), "l"(b), "l"(c));
    return d;
}
__device__ __forceinline__ ull fadd2(ull a, ull b) {
    ull d;
    asm("add.rn.f32x2 %0, %1, %2;" : "=l"(d) : "l"(a), "l"(b));
    return d;
}
__device__ __forceinline__ ull fmul2(ull a, ull b) {
    ull d;
    asm("mul.rn.f32x2 %0, %1, %2;" : "=l"(d) : "l"(a), "l"(b));
    return d;
}
__device__ __forceinline__ ull fpack2(float lo, float hi) {
    ull d;
    asm("mov.b64 %0, {%1, %2};" : "=l"(d) : "f"(lo), "f"(hi));
    return d;
}
__device__ __forceinline__ void funpack2(ull v, float& lo, float& hi) {
    asm("mov.b64 {%0, %1}, %2;" : "=f"(lo), "=f"(hi) : "l"(v));
}
__device__ __forceinline__ ull fdup2(float x) { return fpack2(x, x); }

// ---------------------------------------------------------------
// Phase 1 (r13 version): register-blocked packed MLP+LN.
// 8 warps/block; each warp processes an 8-token tile.
// Tokens packed in pairs into f32x2; weights fetched once per row
// and reused across all 8 tokens of the tile.
// Grid = 148: one balanced wave (1 block/SM; 125.5 KB smem/block).
// ---------------------------------------------------------------
#define HP_STRIDE 10   // pad: row stride (floats) for h tile
#define AP_STRIDE 10   // pad: row stride (floats) for activation tile

__global__ __launch_bounds__(256) void phase1_kernel(
    const int*   __restrict__ seq,
    const float* __restrict__ embed,
    const float* __restrict__ W1,
    const float* __restrict__ b1,
    const float* __restrict__ W2,
    const float* __restrict__ b2,
    const float* __restrict__ gamma,
    const float* __restrict__ beta)
{
    extern __shared__ float dsm[];
    float* W1s = dsm;            // 64*128
    float* W2s = dsm + 64 * 128; // 128*64

    __shared__ __align__(16) float b1s[128];
    __shared__ float b2s[64], gs[64], bs[64];
    __shared__ __align__(8) float hpf[8][64][HP_STRIDE];   // h tile  [dim][token]
    __shared__ __align__(8) float apf[8][128][AP_STRIDE];  // act tile [m][token]

    const int tid = threadIdx.x;
    for (int i = tid; i < 64 * 128; i += 256) W1s[i] = W1[i];
    for (int i = tid; i < 128 * 64; i += 256) W2s[i] = W2[i];
    if (tid < 128) b1s[tid] = b1[tid];
    if (tid < 64) { b2s[tid] = b2[tid]; gs[tid] = gamma[tid]; bs[tid] = beta[tid]; }
    __syncthreads();

    const int w    = tid >> 5;
    const int lane = tid & 31;
    const int gw   = blockIdx.x * 8 + w;     // global warp id
    const int nw   = gridDim.x * 8;

    const ull negone = fdup2(-1.0f);
    const ull inv64  = fdup2(1.0f / 64.0f);

    for (int tile = gw; tile < NTOK / 8; tile += nw) {
        const int tok0 = tile * 8;

        // ---- gather: hpf[j][tt] = embed[seq[tok0+tt]][j] ----
        #pragma unroll
        for (int tt = 0; tt < 8; tt++) {
            const int v = seq[tok0 + tt];
            hpf[w][lane][tt]      = embed[v * 64 + lane];
            hpf[w][lane + 32][tt] = embed[v * 64 + 32 + lane];
        }
        __syncwarp();

        // ---- layer 1: a[m] = relu(sum_j h[j]*W1[j,m] + b1[m]) ----
        // lane owns outputs m = 4*lane..+3; acc[p][o] packs token pair p.
        ull acc[4][4];
        {
            const float4 bb4 = *(const float4*)&b1s[lane * 4];
            #pragma unroll
            for (int p = 0; p < 4; p++) {
                acc[p][0] = fdup2(bb4.x); acc[p][1] = fdup2(bb4.y);
                acc[p][2] = fdup2(bb4.z); acc[p][3] = fdup2(bb4.w);
            }
        }
        #pragma unroll 8
        for (int j = 0; j < 64; j++) {
            const float4 w4 = *(const float4*)&W1s[j * 128 + lane * 4];
            const ull wd0 = fdup2(w4.x), wd1 = fdup2(w4.y);
            const ull wd2 = fdup2(w4.z), wd3 = fdup2(w4.w);
            #pragma unroll
            for (int p = 0; p < 4; p++) {
                const ull hj = *(const ull*)&hpf[w][j][2 * p];  // broadcast
                acc[p][0] = ffma2(hj, wd0, acc[p][0]);
                acc[p][1] = ffma2(hj, wd1, acc[p][1]);
                acc[p][2] = ffma2(hj, wd2, acc[p][2]);
                acc[p][3] = ffma2(hj, wd3, acc[p][3]);
            }
        }
        // relu + store activations
        #pragma unroll
        for (int p = 0; p < 4; p++)
            #pragma unroll
            for (int o = 0; o < 4; o++) {
                float lo, hi;
                funpack2(acc[p][o], lo, hi);
                *(ull*)&apf[w][lane * 4 + o][2 * p] =
                    fpack2(fmaxf(lo, 0.f), fmaxf(hi, 0.f));
            }
        __syncwarp();

        // ---- layer 2: f[i] = sum_m a[m]*W2[m,i] + b2[i]; lane owns i=2l,2l+1 ----
        ull a2[2][4];
        {
            const float2 bb2 = *(const float2*)&b2s[2 * lane];
            #pragma unroll
            for (int p = 0; p < 4; p++) {
                a2[0][p] = fdup2(bb2.x);
                a2[1][p] = fdup2(bb2.y);
            }
        }
        #pragma unroll 8
        for (int m = 0; m < 128; m++) {
            const float2 w2 = *(const float2*)&W2s[m * 64 + 2 * lane];
            const ull wd0 = fdup2(w2.x), wd1 = fdup2(w2.y);
            #pragma unroll
            for (int p = 0; p < 4; p++) {
                const ull am = *(const ull*)&apf[w][m][2 * p];  // broadcast
                a2[0][p] = ffma2(am, wd0, a2[0][p]);
                a2[1][p] = ffma2(am, wd1, a2[1][p]);
            }
        }

        // ---- residual + LayerNorm (packed over token pairs) ----
        ull xp[2][4];
        #pragma unroll
        for (int o = 0; o < 2; o++)
            #pragma unroll
            for (int p = 0; p < 4; p++) {
                const ull hv = *(const ull*)&hpf[w][2 * lane + o][2 * p];
                xp[o][p] = fadd2(a2[o][p], hv);
            }

        // mean over 64 dims per token (packed pair reduce)
        ull mu2[4], rstd2[4];
        #pragma unroll
        for (int p = 0; p < 4; p++) {
            ull s = fadd2(xp[0][p], xp[1][p]);
            #pragma unroll
            for (int off = 16; off > 0; off >>= 1) {
                float lo, hi;
                funpack2(s, lo, hi);
                lo += __shfl_xor_sync(0xffffffffu, lo, off);
                hi += __shfl_xor_sync(0xffffffffu, hi, off);
                s = fpack2(lo, hi);
            }
            mu2[p] = fmul2(s, inv64);
        }
        // variance
        #pragma unroll
        for (int p = 0; p < 4; p++) {
            const ull d0 = ffma2(mu2[p], negone, xp[0][p]);
            const ull d1 = ffma2(mu2[p], negone, xp[1][p]);
            ull s = fadd2(ffma2(d0, d0, 0ull), ffma2(d1, d1, 0ull));
            #pragma unroll
            for (int off = 16; off > 0; off >>= 1) {
                float lo, hi;
                funpack2(s, lo, hi);
                lo += __shfl_xor_sync(0xffffffffu, lo, off);
                hi += __shfl_xor_sync(0xffffffffu, hi, off);
                s = fpack2(lo, hi);
            }
            float vlo, vhi;
            funpack2(fmul2(s, inv64), vlo, vhi);
            rstd2[p] = fpack2(rsqrtf(vlo + 1e-5f), rsqrtf(vhi + 1e-5f));
        }
        // y = (x - mu) * rstd * gamma + beta; scatter to g_h
        #pragma unroll
        for (int o = 0; o < 2; o++) {
            const ull gm = fdup2(gs[2 * lane + o]);
            const ull bt = fdup2(bs[2 * lane + o]);
            #pragma unroll
            for (int p = 0; p < 4; p++) {
                const ull d  = ffma2(mu2[p], negone, xp[o][p]);
                const ull t  = fmul2(fmul2(d, rstd2[p]), gm);
                const ull y  = fadd2(t, bt);
                float lo, hi;
                funpack2(y, lo, hi);
                g_h[(tok0 + 2 * p)     * 64 + 2 * lane + o] = lo;
                g_h[(tok0 + 2 * p + 1) * 64 + 2 * lane + o] = hi;
            }
        }
        __syncwarp();
    }
}

// ---------------------------------------------------------------
// Phase 1.5: Gram lookahead. Warp per token; 8 four-lane groups,
// group j computes dot(k_t, k_{t-j}); j=0 -> invd in slot 7.
// ---------------------------------------------------------------
__global__ __launch_bounds__(256) void gram_kernel()
{
    const int wid  = (blockIdx.x * 256 + threadIdx.x) >> 5;
    const int lane = threadIdx.x & 31;
    if (wid >= NTOK) return;
    const int t   = wid;
    const int pos = t & (LSEQ - 1);
    const int j   = lane >> 2;     // 0..7
    const int sub = lane & 3;      // elems [sub*16, sub*16+16)

    const bool valid = (j == 0) || (pos >= j);
    const int  tm    = valid ? (t - j) : t;

    const ull* pa = (const ull*)&g_h[(size_t)t  * 64 + sub * 16];
    const ull* pb = (const ull*)&g_h[(size_t)tm * 64 + sub * 16];

    ull a0 = 0ull, a1 = 0ull, a2 = 0ull, a3 = 0ull;
    #pragma unroll
    for (int i = 0; i < 8; i += 4) {
        a0 = ffma2(pa[i],     pb[i],     a0);
        a1 = ffma2(pa[i + 1], pb[i + 1], a1);
        a2 = ffma2(pa[i + 2], pb[i + 2], a2);
        a3 = ffma2(pa[i + 3], pb[i + 3], a3);
    }
    float lo, hi;
    funpack2(fadd2(fadd2(a0, a1), fadd2(a2, a3)), lo, hi);
    float s = lo + hi;
    s += __shfl_xor_sync(0xffffffffu, s, 1);
    s += __shfl_xor_sync(0xffffffffu, s, 2);

    if (sub == 0) {
        if (j == 0) g_gram[(size_t)t * 8 + 7] = 1.0f / (s + 1e-6f);
        else        g_gram[(size_t)t * 8 + (j - 1)] = valid ? s : 0.0f;
    }
}

// ---------------------------------------------------------------
// Phase 2: delta-rule scan, rank-8 windows, pipelined dots.
// (r12/r13 version — known good, no fused epilogue)
// ---------------------------------------------------------------
__global__ __launch_bounds__(32, 1) void scan_kernel()
{
    __shared__ __align__(16) float smk[RING][64];
    __shared__ __align__(16) float smaux[RING][8];  // g1..g7, invd

    const int bb   = blockIdx.x >> 4;
    const int rg   = blockIdx.x & 15;
    const int tid  = threadIdx.x;   // 0..31
    const int r    = tid >> 3;      // row within group 0..3
    const int c8   = tid & 7;       // column eighth
    const int e    = rg * 4 + r;

    const float* __restrict__ hb  = g_h    + (size_t)bb * LSEQ * HD;
    const float* __restrict__ gga = g_gram + (size_t)bb * LSEQ * 8;

    #pragma unroll
    for (int i = tid; i < 24 * 16; i += 32) {
        const int tok = i >> 4, seg = i & 15;
        *(float4*)&smk[tok][seg * 4] = *(const float4*)&hb[tok * 64 + seg * 4];
    }
    #pragma unroll
    for (int i = tid; i < 48; i += 32) {
        const int tok = i >> 1, hf = i & 1;
        *(float4*)&smaux[tok][hf * 4] = *(const float4*)&gga[tok * 8 + hf * 4];
    }
    __syncwarp();

    ull M[4];
    #pragma unroll
    for (int i = 0; i < 4; i++) M[i] = 0ull;

    ull kreg[8][4];
    #pragma unroll
    for (int u = 0; u < 8; u++) {
        const ulonglong2* kp = (const ulonglong2*)&smk[u][c8 * 8];
        const ulonglong2 k0 = kp[0], k1 = kp[1];
        kreg[u][0] = k0.x; kreg[u][1] = k0.y;
        kreg[u][2] = k1.x; kreg[u][3] = k1.y;
    }

    float c[8], dv[8];
    #pragma unroll
    for (int i = 0; i < 8; i++) c[i] = 0.0f;

    #pragma unroll 1
    for (int tb = 0; tb <= 2032; tb += 8) {
        #pragma unroll
        for (int u = 0; u < 8; u++) {
            const int sl = (tb + u) & (RING - 1);
            const float  ke = smk[sl][e];
            const float4 gA = *(const float4*)&smaux[sl][0];
            const float4 gB = *(const float4*)&smaux[sl][4];
            float S = c[u];
            if (u >= 7) S = fmaf(dv[u - 7], gB.z, S);
            if (u >= 6) S = fmaf(dv[u - 6], gB.y, S);
            if (u >= 5) S = fmaf(dv[u - 5], gB.x, S);
            if (u >= 4) S = fmaf(dv[u - 4], gA.w, S);
            if (u >= 3) S = fmaf(dv[u - 3], gA.z, S);
            if (u >= 2) S = fmaf(dv[u - 2], gA.y, S);
            if (u >= 1) S = fmaf(dv[u - 1], gA.x, S);
            dv[u] = fmaf(-gB.w, S, ke);
        }

        #pragma unroll
        for (int u = 0; u < 8; u++) {
            const ull dvp = fpack2(dv[u], dv[u]);
            M[0] = ffma2(dvp, kreg[u][0], M[0]);
            M[1] = ffma2(dvp, kreg[u][1], M[1]);
            M[2] = ffma2(dvp, kreg[u][2], M[2]);
            M[3] = ffma2(dvp, kreg[u][3], M[3]);
        }

        #pragma unroll
        for (int u = 0; u < 8; u++) {
            const ulonglong2* kd =
                (const ulonglong2*)&smk[(tb + 8 + u) & (RING - 1)][c8 * 8];
            const ulonglong2 k0 = kd[0], k1 = kd[1];
            kreg[u][0] = k0.x; kreg[u][1] = k0.y;
            kreg[u][2] = k1.x; kreg[u][3] = k1.y;
            ull a0 = ffma2(M[0], k0.x, 0ull);
            ull a1 = ffma2(M[1], k0.y, 0ull);
            a0 = ffma2(M[2], k1.x, a0);
            a1 = ffma2(M[3], k1.y, a1);
            float lo, hi;
            funpack2(fadd2(a0, a1), lo, hi);
            c[u] = lo + hi;
        }
        #pragma unroll
        for (int u = 0; u < 8; u++) c[u] += __shfl_xor_sync(0xffffffffu, c[u], 1);
        #pragma unroll
        for (int u = 0; u < 8; u++) c[u] += __shfl_xor_sync(0xffffffffu, c[u], 2);
        #pragma unroll
        for (int u = 0; u < 8; u++) c[u] += __shfl_xor_sync(0xffffffffu, c[u], 4);

        #pragma unroll
        for (int w = 0; w < 4; w++) {
            const int i = w * 32 + tid;
            const int tok = tb + 24 + (i >> 4);
            const int seg = i & 15;
            *(float4*)&smk[tok & (RING - 1)][seg * 4] =
                *(const float4*)&hb[tok * 64 + seg * 4];
        }
        if (tid < 16) {
            const int tok = tb + 24 + (tid >> 1);
            const int hf  = tid & 1;
            *(float4*)&smaux[tok & (RING - 1)][hf * 4] =
                *(const float4*)&gga[tok * 8 + hf * 4];
        }
        __syncwarp();
    }

    {
        const int tb = 2040;
        #pragma unroll
        for (int u = 0; u < 7; u++) {
            const int sl = (tb + u) & (RING - 1);
            const float  ke = smk[sl][e];
            const float4 gA = *(const float4*)&smaux[sl][0];
            const float4 gB = *(const float4*)&smaux[sl][4];
            float S = c[u];
            if (u >= 6) S = fmaf(dv[u - 6], gB.y, S);
            if (u >= 5) S = fmaf(dv[u - 5], gB.x, S);
            if (u >= 4) S = fmaf(dv[u - 4], gA.w, S);
            if (u >= 3) S = fmaf(dv[u - 3], gA.z, S);
            if (u >= 2) S = fmaf(dv[u - 2], gA.y, S);
            if (u >= 1) S = fmaf(dv[u - 1], gA.x, S);
            dv[u] = fmaf(-gB.w, S, ke);
        }

        const float4 gA = *(const float4*)&smaux[2047 & (RING - 1)][0];
        const float4 gB = *(const float4*)&smaux[2047 & (RING - 1)][4];
        float S = c[7];
        S = fmaf(dv[0], gB.z, S);
        S = fmaf(dv[1], gB.y, S);
        S = fmaf(dv[2], gB.x, S);
        S = fmaf(dv[3], gA.w, S);
        S = fmaf(dv[4], gA.z, S);
        S = fmaf(dv[5], gA.y, S);
        S = fmaf(dv[6], gA.x, S);
        if (c8 == 0) g_ctx[bb * 64 + e] = S;
    }
}

// ---------------------------------------------------------------
// Phase 3: out = (ctx @ Wr + br) @ Wo + bo
// ---------------------------------------------------------------
__global__ __launch_bounds__(64) void proj_kernel(
    const float* __restrict__ Wr, const float* __restrict__ br,
    const float* __restrict__ Wo, const float* __restrict__ bo,
    float* __restrict__ out)
{
    __shared__ float cs[64], rs[64];
    const int b   = blockIdx.x;
    const int tid = threadIdx.x;
    cs[tid] = g_ctx[b * 64 + tid];
    __syncthreads();
    float rr = br[tid];
    #pragma unroll 8
    for (int j = 0; j < 64; j++) rr = fmaf(cs[j], Wr[j * 64 + tid], rr);
    rs[tid] = rr;
    __syncthreads();
    float o = bo[tid];
    #pragma unroll 8
    for (int j = 0; j < 64; j++) o = fmaf(rs[j], Wo[j * 64 + tid], o);
    out[b * 64 + tid] = o;
}

// ---------------------------------------------------------------
extern "C" void kernel_launch(void* const* d_in, const int* in_sizes, int n_in,
                              void* d_out, int out_size)
{
    const int*   seq   = (const int*)  d_in[0];
    const float* embed = (const float*)d_in[1];
    const float* W1    = (const float*)d_in[2];
    const float* b1    = (const float*)d_in[3];
    const float* W2    = (const float*)d_in[4];
    const float* b2    = (const float*)d_in[5];
    const float* gamma = (const float*)d_in[6];
    const float* beta  = (const float*)d_in[7];
    const float* Wr    = (const float*)d_in[8];
    const float* br    = (const float*)d_in[9];
    const float* Wo    = (const float*)d_in[10];
    const float* bo    = (const float*)d_in[11];
    float* out = (float*)d_out;

    (void)in_sizes; (void)n_in; (void)out_size;

    cudaFuncSetAttribute(phase1_kernel,
                         cudaFuncAttributeMaxDynamicSharedMemorySize, 65536);
    phase1_kernel<<<148, 256, 65536>>>(seq, embed, W1, b1, W2, b2, gamma, beta);
    gram_kernel<<<NTOK / 8, 256>>>();
    scan_kernel<<<BATCH * 16, 32>>>();
    proj_kernel<<<BATCH, 64>>>(Wr, br, Wo, bo, out);
}